// round 2
// baseline (speedup 1.0000x reference)
#include <cuda_runtime.h>
#include <cuda_bf16.h>
#include <cstdint>

#define HW 16384
#define SMEM_BYTES (2*128*264*2)

// ---------------- scratch (device globals; no allocations allowed) ----------
__device__ __nv_bfloat16 g_qkvT[(size_t)8*HW*768];   // [bv][p][768] bf16
__device__ __nv_bfloat16 g_aoT [(size_t)8*HW*256];   // [bv][p][256] bf16
__device__ __nv_bfloat16 g_wqkv[768*256];
__device__ __nv_bfloat16 g_wproj[256*256];
__device__ float g_part[64][8][2];
__device__ float g_mean[64];
__device__ float g_rstd[64];

// ---------------- weight convert -------------------------------------------
__global__ void k_convert(const float* __restrict__ wq, const float* __restrict__ wp){
    int i = blockIdx.x*256 + threadIdx.x;
    if (i < 768*256) g_wqkv[i]  = __float2bfloat16(wq[i]);
    if (i < 256*256) g_wproj[i] = __float2bfloat16(wp[i]);
}

// ---------------- GroupNorm statistics --------------------------------------
// group gi (bv*8+g) covers a contiguous 524288-float region of x.
__global__ void k_stats(const float* __restrict__ x){
    const int gi = blockIdx.x, ck = blockIdx.y, t = threadIdx.x;
    const float4* p = (const float4*)(x + (size_t)gi*524288 + (size_t)ck*65536);
    float s = 0.f, ss = 0.f;
    #pragma unroll 4
    for (int it = 0; it < 64; ++it){
        float4 v = p[it*256 + t];
        s  += v.x + v.y + v.z + v.w;
        ss += v.x*v.x + v.y*v.y + v.z*v.z + v.w*v.w;
    }
    #pragma unroll
    for (int d = 16; d; d >>= 1){
        s  += __shfl_xor_sync(0xffffffffu, s, d);
        ss += __shfl_xor_sync(0xffffffffu, ss, d);
    }
    __shared__ float sh[16];
    if ((t & 31) == 0){ sh[t>>5] = s; sh[8 + (t>>5)] = ss; }
    __syncthreads();
    if (t == 0){
        float S = 0.f, SS = 0.f;
        for (int i = 0; i < 8; ++i){ S += sh[i]; SS += sh[8+i]; }
        g_part[gi][ck][0] = S; g_part[gi][ck][1] = SS;
    }
}

__global__ void k_statfin(){
    const int t = threadIdx.x;   // 64 threads, one per (bv, group)
    float S = 0.f, SS = 0.f;
    for (int i = 0; i < 8; ++i){ S += g_part[t][i][0]; SS += g_part[t][i][1]; }
    const float inv = 1.f/524288.f;
    const float m = S*inv;
    const float v = SS*inv - m*m;       // biased variance
    g_mean[t] = m;
    g_rstd[t] = rsqrtf(v + 1e-5f);
}

// ---------------- bf16 mma.sync helper --------------------------------------
__device__ __forceinline__ void mma_bf16(float c[4], const uint32_t a[4], const uint32_t b[2]){
    asm volatile(
      "mma.sync.aligned.m16n8k16.row.col.f32.bf16.bf16.f32 "
      "{%0,%1,%2,%3},{%4,%5,%6,%7},{%8,%9},{%0,%1,%2,%3};\n"
      : "+f"(c[0]), "+f"(c[1]), "+f"(c[2]), "+f"(c[3])
      : "r"(a[0]), "r"(a[1]), "r"(a[2]), "r"(a[3]), "r"(b[0]), "r"(b[1]));
}

// ---------------- fused GroupNorm-apply + QKV GEMM ---------------------------
// CTA: one bv image, 128-token tile, loops all 6 M-tiles (M=768).
// Bs: xn tile token-major [128 tok][264 pitch] bf16 (the transpose the GEMM wants)
// As: weight tile [128 m][264 pitch] bf16, reloaded per M-tile (hits L2)
__global__ __launch_bounds__(256, 1) void k_qkv(
    const float* __restrict__ x, const float* __restrict__ gamma,
    const float* __restrict__ beta, const float* __restrict__ bqkv)
{
    extern __shared__ __nv_bfloat16 sm[];
    __nv_bfloat16* Bs = sm;            // [128][264]
    __nv_bfloat16* As = sm + 128*264;  // [128][264]
    const int t  = threadIdx.x;
    const int bv = blockIdx.y;
    const int p0 = blockIdx.x * 128;

    // load + normalize x tile into Bs[token][k]
    {
        const int sub   = t >> 5;   // warp -> channel stream
        const int lanep = t & 31;   // lane -> pixel
        for (int it = 0; it < 32; ++it){
            const int c = it*8 + sub;
            const int gidx = bv*8 + (c >> 5);
            const float sc = g_rstd[gidx]*gamma[c];
            const float sh = beta[c] - g_mean[gidx]*sc;
            const float* xrow = x + ((size_t)(bv*256 + c))*HW + p0;
            #pragma unroll
            for (int i = 0; i < 4; ++i){
                const int j = i*32 + lanep;
                Bs[j*264 + c] = __float2bfloat16(xrow[j]*sc + sh);
            }
        }
    }
    __syncthreads();

    const int lane = t & 31, warp = t >> 5;
    const int g = lane >> 2, tq = lane & 3;
    const int wm = (warp & 1) * 64, wn = (warp >> 1) * 32;

    for (int mt = 0; mt < 6; ++mt){
        {   // load A tile (coalesced 16B)
            const int row = t >> 1, seg = t & 1;
            const uint4* src = (const uint4*)(g_wqkv + (mt*128 + row)*256 + seg*128);
            uint4* dst = (uint4*)(As + row*264 + seg*128);
            #pragma unroll
            for (int j = 0; j < 16; ++j) dst[j] = src[j];
        }
        __syncthreads();

        float acc[4][4][4];
        #pragma unroll
        for (int i=0;i<4;i++){
            #pragma unroll
            for (int j=0;j<4;j++){
                #pragma unroll
                for (int r=0;r<4;r++) acc[i][j][r]=0.f;
            }
        }

        for (int k0 = 0; k0 < 256; k0 += 16){
            uint32_t ra[4][4], rb[4][2];
            #pragma unroll
            for (int i = 0; i < 4; ++i){
                const __nv_bfloat16* a0 = As + (wm + i*16 + g)*264 + k0 + tq*2;
                const __nv_bfloat16* a1 = As + (wm + i*16 + 8 + g)*264 + k0 + tq*2;
                ra[i][0] = *(const uint32_t*)a0;
                ra[i][1] = *(const uint32_t*)a1;
                ra[i][2] = *(const uint32_t*)(a0 + 8);
                ra[i][3] = *(const uint32_t*)(a1 + 8);
            }
            #pragma unroll
            for (int j = 0; j < 4; ++j){
                const __nv_bfloat16* bp = Bs + (wn + j*8 + g)*264 + k0 + tq*2;
                rb[j][0] = *(const uint32_t*)bp;
                rb[j][1] = *(const uint32_t*)(bp + 8);
            }
            #pragma unroll
            for (int i = 0; i < 4; ++i){
                #pragma unroll
                for (int j = 0; j < 4; ++j)
                    mma_bf16(acc[i][j], ra[i], rb[j]);
            }
        }
        __syncthreads();

        // bias + stage D as [token][m] bf16 (pitch 136) reusing the As region
        __nv_bfloat16* Ds = As;
        #pragma unroll
        for (int i = 0; i < 4; ++i){
            const int m0 = wm + i*16 + g;
            const float b0 = bqkv[mt*128 + m0];
            const float b1 = bqkv[mt*128 + m0 + 8];
            #pragma unroll
            for (int j = 0; j < 4; ++j){
                const int n0 = wn + j*8 + tq*2;
                Ds[n0*136 + m0]         = __float2bfloat16(acc[i][j][0] + b0);
                Ds[(n0+1)*136 + m0]     = __float2bfloat16(acc[i][j][1] + b0);
                Ds[n0*136 + m0 + 8]     = __float2bfloat16(acc[i][j][2] + b1);
                Ds[(n0+1)*136 + m0 + 8] = __float2bfloat16(acc[i][j][3] + b1);
            }
        }
        __syncthreads();

        {   // coalesced token-major global write
            const int row = t >> 1, seg = t & 1;
            uint4* dst = (uint4*)(g_qkvT + ((size_t)(bv*HW + p0 + row))*768 + mt*128);
            const uint4* src = (const uint4*)(Ds + row*136);
            #pragma unroll
            for (int j = 0; j < 8; ++j) dst[seg*8 + j] = src[seg*8 + j];
        }
        __syncthreads();
    }
}

// ---------------- per-pixel 2x2 cross-view attention -------------------------
__device__ __forceinline__ void load8f(float* o, const __nv_bfloat16* p){
    uint4 u = *(const uint4*)p;
    const __nv_bfloat162* h = (const __nv_bfloat162*)&u;
    #pragma unroll
    for (int i = 0; i < 4; ++i){ float2 f = __bfloat1622float2(h[i]); o[2*i] = f.x; o[2*i+1] = f.y; }
}

__global__ __launch_bounds__(256) void k_attn(){
    const int t = threadIdx.x;
    const int gw = blockIdx.x*8 + (t >> 5);   // one warp per (b, pixel)
    const int b = gw >> 14, p = gw & 16383;
    const int lane = t & 31;
    const int off = (lane >> 3)*64 + (lane & 7)*8;   // head*64 + sub*8
    const __nv_bfloat16* r0 = g_qkvT + ((size_t)(b*2*HW + p))*768;
    const __nv_bfloat16* r1 = r0 + (size_t)HW*768;
    float q0[8],q1[8],k0[8],k1[8],v0[8],v1[8];
    load8f(q0, r0 + off);        load8f(q1, r1 + off);
    load8f(k0, r0 + 256 + off);  load8f(k1, r1 + 256 + off);
    load8f(v0, r0 + 512 + off);  load8f(v1, r1 + 512 + off);
    float s00=0.f, s01=0.f, s10=0.f, s11=0.f;
    #pragma unroll
    for (int j = 0; j < 8; ++j){
        s00 += q0[j]*k0[j]; s01 += q0[j]*k1[j];
        s10 += q1[j]*k0[j]; s11 += q1[j]*k1[j];
    }
    #pragma unroll
    for (int d = 1; d < 8; d <<= 1){   // reduce over the 8-lane head group
        s00 += __shfl_xor_sync(0xffffffffu, s00, d);
        s01 += __shfl_xor_sync(0xffffffffu, s01, d);
        s10 += __shfl_xor_sync(0xffffffffu, s10, d);
        s11 += __shfl_xor_sync(0xffffffffu, s11, d);
    }
    const float sc = 0.125f;   // hd=64 -> 1/sqrt(64)
    const float l00=s00*sc, l01=s01*sc, l10=s10*sc, l11=s11*sc;
    const float m0 = fmaxf(l00,l01), m1 = fmaxf(l10,l11);
    const float e00=__expf(l00-m0), e01=__expf(l01-m0);
    const float e10=__expf(l10-m1), e11=__expf(l11-m1);
    const float i0 = 1.f/(e00+e01), i1 = 1.f/(e10+e11);
    const float a00=e00*i0, a01=e01*i0, a10=e10*i1, a11=e11*i1;
    __align__(16) __nv_bfloat16 o0[8], o1[8];
    #pragma unroll
    for (int j = 0; j < 8; ++j){
        o0[j] = __float2bfloat16(a00*v0[j] + a01*v1[j]);
        o1[j] = __float2bfloat16(a10*v0[j] + a11*v1[j]);
    }
    *(uint4*)(g_aoT + ((size_t)(b*2*HW + p))*256 + off)       = *(const uint4*)o0;
    *(uint4*)(g_aoT + ((size_t)((b*2+1)*HW + p))*256 + off)   = *(const uint4*)o1;
}

// ---------------- proj GEMM + bias + residual --------------------------------
__global__ __launch_bounds__(256, 1) void k_proj(
    const float* __restrict__ x, const float* __restrict__ bproj, float* __restrict__ out)
{
    extern __shared__ __nv_bfloat16 sm[];
    __nv_bfloat16* Bs = sm;            // [128 tok][264]
    __nv_bfloat16* As = sm + 128*264;  // [128 m][264]
    const int t  = threadIdx.x;
    const int bv = blockIdx.y;
    const int p0 = blockIdx.x * 128;

    {   // B tile: attn-out is already token-major K-contiguous
        const int row = t >> 1, seg = t & 1;
        const uint4* src = (const uint4*)(g_aoT + ((size_t)(bv*HW + p0 + row))*256 + seg*128);
        uint4* dst = (uint4*)(Bs + row*264 + seg*128);
        #pragma unroll
        for (int j = 0; j < 16; ++j) dst[j] = src[j];
    }
    __syncthreads();

    const int lane = t & 31, warp = t >> 5;
    const int g = lane >> 2, tq = lane & 3;
    const int wm = (warp & 1) * 64, wn = (warp >> 1) * 32;

    for (int mt = 0; mt < 2; ++mt){
        {
            const int row = t >> 1, seg = t & 1;
            const uint4* src = (const uint4*)(g_wproj + (mt*128 + row)*256 + seg*128);
            uint4* dst = (uint4*)(As + row*264 + seg*128);
            #pragma unroll
            for (int j = 0; j < 16; ++j) dst[j] = src[j];
        }
        __syncthreads();

        float acc[4][4][4];
        #pragma unroll
        for (int i=0;i<4;i++){
            #pragma unroll
            for (int j=0;j<4;j++){
                #pragma unroll
                for (int r=0;r<4;r++) acc[i][j][r]=0.f;
            }
        }

        for (int k0 = 0; k0 < 256; k0 += 16){
            uint32_t ra[4][4], rb[4][2];
            #pragma unroll
            for (int i = 0; i < 4; ++i){
                const __nv_bfloat16* a0 = As + (wm + i*16 + g)*264 + k0 + tq*2;
                const __nv_bfloat16* a1 = As + (wm + i*16 + 8 + g)*264 + k0 + tq*2;
                ra[i][0] = *(const uint32_t*)a0;
                ra[i][1] = *(const uint32_t*)a1;
                ra[i][2] = *(const uint32_t*)(a0 + 8);
                ra[i][3] = *(const uint32_t*)(a1 + 8);
            }
            #pragma unroll
            for (int j = 0; j < 4; ++j){
                const __nv_bfloat16* bp = Bs + (wn + j*8 + g)*264 + k0 + tq*2;
                rb[j][0] = *(const uint32_t*)bp;
                rb[j][1] = *(const uint32_t*)(bp + 8);
            }
            #pragma unroll
            for (int i = 0; i < 4; ++i){
                #pragma unroll
                for (int j = 0; j < 4; ++j)
                    mma_bf16(acc[i][j], ra[i], rb[j]);
            }
        }
        __syncthreads();

        // stage D fp32 as [m][132] in the As region (exactly fits: 128*132*4 == 128*264*2)
        float* Ds = (float*)As;
        #pragma unroll
        for (int i = 0; i < 4; ++i){
            const int m0 = wm + i*16 + g;
            #pragma unroll
            for (int j = 0; j < 4; ++j){
                const int n0 = wn + j*8 + tq*2;
                Ds[m0*132 + n0]       = acc[i][j][0];
                Ds[m0*132 + n0 + 1]   = acc[i][j][1];
                Ds[(m0+8)*132 + n0]     = acc[i][j][2];
                Ds[(m0+8)*132 + n0 + 1] = acc[i][j][3];
            }
        }
        __syncthreads();

        {   // bias + residual + coalesced NCHW fp32 store
            const int row = t >> 1;
            const int off = (t & 1) * 64;
            const int ch = mt*128 + row;
            const float bias = bproj[ch];
            const size_t gix = ((size_t)(bv*256 + ch))*HW + p0 + off;
            const float4* xs = (const float4*)(x + gix);
            float4* os = (float4*)(out + gix);
            const float4* ds = (const float4*)(Ds + row*132 + off);
            #pragma unroll
            for (int j = 0; j < 16; ++j){
                float4 d = ds[j], xv = xs[j];
                os[j] = make_float4(xv.x + d.x + bias, xv.y + d.y + bias,
                                    xv.z + d.z + bias, xv.w + d.w + bias);
            }
        }
        __syncthreads();
    }
}

// ---------------- launch ------------------------------------------------------
extern "C" void kernel_launch(void* const* d_in, const int* in_sizes, int n_in,
                              void* d_out, int out_size)
{
    const float* x     = (const float*)d_in[0];
    const float* gam   = (const float*)d_in[1];
    const float* bet   = (const float*)d_in[2];
    const float* wqkv  = (const float*)d_in[3];
    const float* bqkv  = (const float*)d_in[4];
    const float* wproj = (const float*)d_in[5];
    const float* bproj = (const float*)d_in[6];
    float* out = (float*)d_out;

    cudaFuncSetAttribute(k_qkv,  cudaFuncAttributeMaxDynamicSharedMemorySize, SMEM_BYTES);
    cudaFuncSetAttribute(k_proj, cudaFuncAttributeMaxDynamicSharedMemorySize, SMEM_BYTES);

    k_convert<<<768, 256>>>(wqkv, wproj);
    k_stats<<<dim3(64, 8), 256>>>(x);
    k_statfin<<<1, 64>>>();
    k_qkv<<<dim3(128, 8), 256, SMEM_BYTES>>>(x, gam, bet, bqkv);
    k_attn<<<8192, 256>>>();
    k_proj<<<dim3(128, 8), 256, SMEM_BYTES>>>(x, bproj, out);
}

// round 4
// speedup vs baseline: 1.0206x; 1.0206x over previous
#include <cuda_runtime.h>
#include <cuda_bf16.h>
#include <cstdint>

#define HW 16384
#define PITCH 264
#define SMEM_BYTES (2*128*PITCH*2)

// ---------------- scratch (device globals; no allocations allowed) ----------
__device__ __nv_bfloat16 g_qkvT[(size_t)8*HW*768];   // [bv][p][768] bf16
__device__ __nv_bfloat16 g_aoT [(size_t)8*HW*256];   // [bv][p][256] bf16
__device__ __nv_bfloat16 g_wqkv[768*256];
__device__ __nv_bfloat16 g_wproj[256*256];
__device__ float g_part[64][8][2];
__device__ float g_mean[64];
__device__ float g_rstd[64];

// ---------------- helpers ----------------------------------------------------
__device__ __forceinline__ uint32_t s2u(const void* p){
    return (uint32_t)__cvta_generic_to_shared(p);
}
__device__ __forceinline__ void ldsm4(uint32_t r[4], uint32_t addr){
    asm volatile("ldmatrix.sync.aligned.m8n8.x4.shared.b16 {%0,%1,%2,%3}, [%4];"
        : "=r"(r[0]), "=r"(r[1]), "=r"(r[2]), "=r"(r[3]) : "r"(addr));
}
__device__ __forceinline__ void mma_bf16(float c[4], const uint32_t a[4],
                                         uint32_t b0, uint32_t b1){
    asm volatile(
      "mma.sync.aligned.m16n8k16.row.col.f32.bf16.bf16.f32 "
      "{%0,%1,%2,%3},{%4,%5,%6,%7},{%8,%9},{%0,%1,%2,%3};\n"
      : "+f"(c[0]), "+f"(c[1]), "+f"(c[2]), "+f"(c[3])
      : "r"(a[0]), "r"(a[1]), "r"(a[2]), "r"(a[3]), "r"(b0), "r"(b1));
}

// ---------------- weight convert -------------------------------------------
__global__ void k_convert(const float* __restrict__ wq, const float* __restrict__ wp){
    int i = blockIdx.x*256 + threadIdx.x;
    if (i < 768*256) g_wqkv[i]  = __float2bfloat16(wq[i]);
    if (i < 256*256) g_wproj[i] = __float2bfloat16(wp[i]);
}

// ---------------- GroupNorm statistics --------------------------------------
__global__ void k_stats(const float* __restrict__ x){
    const int gi = blockIdx.x, ck = blockIdx.y, t = threadIdx.x;
    const float4* p = (const float4*)(x + (size_t)gi*524288 + (size_t)ck*65536);
    float s = 0.f, ss = 0.f;
    #pragma unroll 4
    for (int it = 0; it < 64; ++it){
        float4 v = p[it*256 + t];
        s  += v.x + v.y + v.z + v.w;
        ss += v.x*v.x + v.y*v.y + v.z*v.z + v.w*v.w;
    }
    #pragma unroll
    for (int d = 16; d; d >>= 1){
        s  += __shfl_xor_sync(0xffffffffu, s, d);
        ss += __shfl_xor_sync(0xffffffffu, ss, d);
    }
    __shared__ float sh[16];
    if ((t & 31) == 0){ sh[t>>5] = s; sh[8 + (t>>5)] = ss; }
    __syncthreads();
    if (t == 0){
        float S = 0.f, SS = 0.f;
        for (int i = 0; i < 8; ++i){ S += sh[i]; SS += sh[8+i]; }
        g_part[gi][ck][0] = S; g_part[gi][ck][1] = SS;
    }
}

__global__ void k_statfin(){
    const int t = threadIdx.x;   // 64 threads, one per (bv, group)
    float S = 0.f, SS = 0.f;
    for (int i = 0; i < 8; ++i){ S += g_part[t][i][0]; SS += g_part[t][i][1]; }
    const float inv = 1.f/524288.f;
    const float m = S*inv;
    const float v = SS*inv - m*m;       // biased variance
    g_mean[t] = m;
    g_rstd[t] = rsqrtf(v + 1e-5f);
}

// ---------------- fused GroupNorm-apply + QKV GEMM ---------------------------
// 512 threads / 16 warps. Warp tile 32(m) x 32(tok). ldmatrix fragment loads,
// double-buffered over the K loop.
__global__ __launch_bounds__(512, 1) void k_qkv(
    const float* __restrict__ x, const float* __restrict__ gamma,
    const float* __restrict__ beta, const float* __restrict__ bqkv)
{
    extern __shared__ __nv_bfloat16 sm[];
    __nv_bfloat16* Bs = sm;              // [128 tok][PITCH]
    __nv_bfloat16* As = sm + 128*PITCH;  // [128 m][PITCH]
    const int t  = threadIdx.x;
    const int bv = blockIdx.y;
    const int p0 = blockIdx.x * 128;

    // load + normalize x tile into Bs[token][k] (paired-channel 4B stores)
    {
        const int sub   = t >> 5;   // warp -> channel-pair stream (16 warps)
        const int lanep = t & 31;   // lane -> pixel
        #pragma unroll
        for (int it = 0; it < 8; ++it){
            const int c = (it*16 + sub) * 2;
            const int gidx = bv*8 + (c >> 5);
            const float mu = g_mean[gidx], r = g_rstd[gidx];
            const float sc0 = r*gamma[c],   sh0 = beta[c]   - mu*sc0;
            const float sc1 = r*gamma[c+1], sh1 = beta[c+1] - mu*sc1;
            const float* x0 = x + ((size_t)(bv*256 + c))*HW + p0;
            const float* x1 = x0 + HW;
            #pragma unroll
            for (int i = 0; i < 4; ++i){
                const int j = i*32 + lanep;
                __nv_bfloat162 v = __floats2bfloat162_rn(x0[j]*sc0 + sh0, x1[j]*sc1 + sh1);
                *(__nv_bfloat162*)(Bs + j*PITCH + c) = v;
            }
        }
    }
    __syncthreads();

    const int lane = t & 31, warp = t >> 5;
    const int g = lane >> 2, tq = lane & 3;
    const int wm = (warp & 3) * 32, wn = (warp >> 2) * 32;

    // ldmatrix per-lane base addresses
    const int lrow  = lane & 15;
    const int khalf = lane >> 4;           // 0/1 -> +16B (k columns 8..15)
    uint32_t aBase[2], bBase[2];
    #pragma unroll
    for (int i = 0; i < 2; ++i)
        aBase[i] = s2u(As + (wm + i*16 + lrow)*PITCH) + khalf*16;
    #pragma unroll
    for (int jp = 0; jp < 2; ++jp)
        bBase[jp] = s2u(Bs + (wn + jp*16 + lrow)*PITCH) + khalf*16;

    for (int mt = 0; mt < 6; ++mt){
        {   // load A tile (coalesced 16B)
            const int row = t >> 2, seg = t & 3;
            const uint4* src = (const uint4*)(g_wqkv + (mt*128 + row)*256 + seg*64);
            uint4* dst = (uint4*)(As + row*PITCH + seg*64);
            #pragma unroll
            for (int j = 0; j < 8; ++j) dst[j] = src[j];
        }
        __syncthreads();

        float acc[2][4][4];
        #pragma unroll
        for (int i=0;i<2;i++)
            #pragma unroll
            for (int j=0;j<4;j++)
                #pragma unroll
                for (int r=0;r<4;r++) acc[i][j][r]=0.f;

        uint32_t ra[2][2][4], rb[2][2][4];
        ldsm4(ra[0][0], aBase[0]);
        ldsm4(ra[0][1], aBase[1]);
        ldsm4(rb[0][0], bBase[0]);
        ldsm4(rb[0][1], bBase[1]);

        int buf = 0;
        #pragma unroll 4
        for (int k0 = 16; k0 <= 256; k0 += 16){
            if (k0 < 256){
                const int nb = buf ^ 1;
                ldsm4(ra[nb][0], aBase[0] + k0*2);
                ldsm4(ra[nb][1], aBase[1] + k0*2);
                ldsm4(rb[nb][0], bBase[0] + k0*2);
                ldsm4(rb[nb][1], bBase[1] + k0*2);
            }
            #pragma unroll
            for (int i = 0; i < 2; ++i)
                #pragma unroll
                for (int j = 0; j < 4; ++j)
                    mma_bf16(acc[i][j], ra[buf][i],
                             rb[buf][j>>1][j&1], rb[buf][j>>1][2 + (j&1)]);
            buf ^= 1;
        }
        __syncthreads();

        // bias + stage D as [token][m] bf16 (pitch 136) reusing the As region
        __nv_bfloat16* Ds = As;
        #pragma unroll
        for (int i = 0; i < 2; ++i){
            const int m0 = wm + i*16 + g;
            const float b0 = bqkv[mt*128 + m0];
            const float b1 = bqkv[mt*128 + m0 + 8];
            #pragma unroll
            for (int j = 0; j < 4; ++j){
                const int n0 = wn + j*8 + tq*2;
                Ds[n0*136 + m0]         = __float2bfloat16(acc[i][j][0] + b0);
                Ds[(n0+1)*136 + m0]     = __float2bfloat16(acc[i][j][1] + b0);
                Ds[n0*136 + m0 + 8]     = __float2bfloat16(acc[i][j][2] + b1);
                Ds[(n0+1)*136 + m0 + 8] = __float2bfloat16(acc[i][j][3] + b1);
            }
        }
        __syncthreads();

        {   // coalesced token-major global write
            const int row = t >> 2, seg = t & 3;
            uint4* dst = (uint4*)(g_qkvT + ((size_t)(bv*HW + p0 + row))*768 + mt*128 + seg*32);
            const uint4* src = (const uint4*)(Ds + row*136 + seg*32);
            #pragma unroll
            for (int j = 0; j < 4; ++j) dst[j] = src[j];
        }
        __syncthreads();
    }
}

// ---------------- per-pixel 2x2 cross-view attention -------------------------
__device__ __forceinline__ void load8f(float* o, const __nv_bfloat16* p){
    uint4 u = *(const uint4*)p;
    const __nv_bfloat162* h = (const __nv_bfloat162*)&u;
    #pragma unroll
    for (int i = 0; i < 4; ++i){ float2 f = __bfloat1622float2(h[i]); o[2*i] = f.x; o[2*i+1] = f.y; }
}

__global__ __launch_bounds__(256) void k_attn(){
    const int t = threadIdx.x;
    const int gw = blockIdx.x*8 + (t >> 5);   // one warp per (b, pixel)
    const int b = gw >> 14, p = gw & 16383;
    const int lane = t & 31;
    const int off = (lane >> 3)*64 + (lane & 7)*8;   // head*64 + sub*8
    const __nv_bfloat16* r0 = g_qkvT + ((size_t)(b*2*HW + p))*768;
    const __nv_bfloat16* r1 = r0 + (size_t)HW*768;
    float q0[8],q1[8],k0[8],k1[8],v0[8],v1[8];
    load8f(q0, r0 + off);        load8f(q1, r1 + off);
    load8f(k0, r0 + 256 + off);  load8f(k1, r1 + 256 + off);
    load8f(v0, r0 + 512 + off);  load8f(v1, r1 + 512 + off);
    float s00=0.f, s01=0.f, s10=0.f, s11=0.f;
    #pragma unroll
    for (int j = 0; j < 8; ++j){
        s00 += q0[j]*k0[j]; s01 += q0[j]*k1[j];
        s10 += q1[j]*k0[j]; s11 += q1[j]*k1[j];
    }
    #pragma unroll
    for (int d = 1; d < 8; d <<= 1){   // reduce over the 8-lane head group
        s00 += __shfl_xor_sync(0xffffffffu, s00, d);
        s01 += __shfl_xor_sync(0xffffffffu, s01, d);
        s10 += __shfl_xor_sync(0xffffffffu, s10, d);
        s11 += __shfl_xor_sync(0xffffffffu, s11, d);
    }
    const float sc = 0.125f;   // hd=64 -> 1/sqrt(64)
    const float l00=s00*sc, l01=s01*sc, l10=s10*sc, l11=s11*sc;
    const float m0 = fmaxf(l00,l01), m1 = fmaxf(l10,l11);
    const float e00=__expf(l00-m0), e01=__expf(l01-m0);
    const float e10=__expf(l10-m1), e11=__expf(l11-m1);
    const float i0 = 1.f/(e00+e01), i1 = 1.f/(e10+e11);
    const float a00=e00*i0, a01=e01*i0, a10=e10*i1, a11=e11*i1;
    __align__(16) __nv_bfloat16 o0[8], o1[8];
    #pragma unroll
    for (int j = 0; j < 8; ++j){
        o0[j] = __float2bfloat16(a00*v0[j] + a01*v1[j]);
        o1[j] = __float2bfloat16(a10*v0[j] + a11*v1[j]);
    }
    *(uint4*)(g_aoT + ((size_t)(b*2*HW + p))*256 + off)       = *(const uint4*)o0;
    *(uint4*)(g_aoT + ((size_t)((b*2+1)*HW + p))*256 + off)   = *(const uint4*)o1;
}

// ---------------- proj GEMM + bias + residual --------------------------------
__global__ __launch_bounds__(512, 1) void k_proj(
    const float* __restrict__ x, const float* __restrict__ bproj, float* __restrict__ out)
{
    extern __shared__ __nv_bfloat16 sm[];
    __nv_bfloat16* Bs = sm;              // [128 tok][PITCH]
    __nv_bfloat16* As = sm + 128*PITCH;  // [128 m][PITCH]
    const int t  = threadIdx.x;
    const int bv = blockIdx.y;
    const int p0 = blockIdx.x * 128;

    {   // B tile: attn-out is token-major K-contiguous
        const int row = t >> 2, seg = t & 3;
        const uint4* src = (const uint4*)(g_aoT + ((size_t)(bv*HW + p0 + row))*256 + seg*64);
        uint4* dst = (uint4*)(Bs + row*PITCH + seg*64);
        #pragma unroll
        for (int j = 0; j < 8; ++j) dst[j] = src[j];
    }
    __syncthreads();

    const int lane = t & 31, warp = t >> 5;
    const int g = lane >> 2, tq = lane & 3;
    const int wm = (warp & 3) * 32, wn = (warp >> 2) * 32;

    const int lrow  = lane & 15;
    const int khalf = lane >> 4;
    uint32_t aBase[2], bBase[2];
    #pragma unroll
    for (int i = 0; i < 2; ++i)
        aBase[i] = s2u(As + (wm + i*16 + lrow)*PITCH) + khalf*16;
    #pragma unroll
    for (int jp = 0; jp < 2; ++jp)
        bBase[jp] = s2u(Bs + (wn + jp*16 + lrow)*PITCH) + khalf*16;

    for (int mt = 0; mt < 2; ++mt){
        {
            const int row = t >> 2, seg = t & 3;
            const uint4* src = (const uint4*)(g_wproj + (mt*128 + row)*256 + seg*64);
            uint4* dst = (uint4*)(As + row*PITCH + seg*64);
            #pragma unroll
            for (int j = 0; j < 8; ++j) dst[j] = src[j];
        }
        __syncthreads();

        float acc[2][4][4];
        #pragma unroll
        for (int i=0;i<2;i++)
            #pragma unroll
            for (int j=0;j<4;j++)
                #pragma unroll
                for (int r=0;r<4;r++) acc[i][j][r]=0.f;

        uint32_t ra[2][2][4], rb[2][2][4];
        ldsm4(ra[0][0], aBase[0]);
        ldsm4(ra[0][1], aBase[1]);
        ldsm4(rb[0][0], bBase[0]);
        ldsm4(rb[0][1], bBase[1]);

        int buf = 0;
        #pragma unroll 4
        for (int k0 = 16; k0 <= 256; k0 += 16){
            if (k0 < 256){
                const int nb = buf ^ 1;
                ldsm4(ra[nb][0], aBase[0] + k0*2);
                ldsm4(ra[nb][1], aBase[1] + k0*2);
                ldsm4(rb[nb][0], bBase[0] + k0*2);
                ldsm4(rb[nb][1], bBase[1] + k0*2);
            }
            #pragma unroll
            for (int i = 0; i < 2; ++i)
                #pragma unroll
                for (int j = 0; j < 4; ++j)
                    mma_bf16(acc[i][j], ra[buf][i],
                             rb[buf][j>>1][j&1], rb[buf][j>>1][2 + (j&1)]);
            buf ^= 1;
        }
        __syncthreads();

        // stage D fp32 as [m][132] in the As region (128*132*4 == 128*264*2)
        float* Ds = (float*)As;
        #pragma unroll
        for (int i = 0; i < 2; ++i){
            const int m0 = wm + i*16 + g;
            #pragma unroll
            for (int j = 0; j < 4; ++j){
                const int n0 = wn + j*8 + tq*2;
                Ds[m0*132 + n0]         = acc[i][j][0];
                Ds[m0*132 + n0 + 1]     = acc[i][j][1];
                Ds[(m0+8)*132 + n0]     = acc[i][j][2];
                Ds[(m0+8)*132 + n0 + 1] = acc[i][j][3];
            }
        }
        __syncthreads();

        {   // bias + residual + coalesced NCHW fp32 store
            const int row = t >> 2;
            const int off = (t & 3) * 32;
            const int ch = mt*128 + row;
            const float bias = bproj[ch];
            const size_t gix = ((size_t)(bv*256 + ch))*HW + p0 + off;
            const float4* xs = (const float4*)(x + gix);
            float4* os = (float4*)(out + gix);
            const float4* ds = (const float4*)(Ds + row*132 + off);
            #pragma unroll
            for (int j = 0; j < 8; ++j){
                float4 d = ds[j], xv = xs[j];
                os[j] = make_float4(xv.x + d.x + bias, xv.y + d.y + bias,
                                    xv.z + d.z + bias, xv.w + d.w + bias);
            }
        }
        __syncthreads();
    }
}

// ---------------- launch ------------------------------------------------------
extern "C" void kernel_launch(void* const* d_in, const int* in_sizes, int n_in,
                              void* d_out, int out_size)
{
    const float* x     = (const float*)d_in[0];
    const float* gam   = (const float*)d_in[1];
    const float* bet   = (const float*)d_in[2];
    const float* wqkv  = (const float*)d_in[3];
    const float* bqkv  = (const float*)d_in[4];
    const float* wproj = (const float*)d_in[5];
    const float* bproj = (const float*)d_in[6];
    float* out = (float*)d_out;

    cudaFuncSetAttribute(k_qkv,  cudaFuncAttributeMaxDynamicSharedMemorySize, SMEM_BYTES);
    cudaFuncSetAttribute(k_proj, cudaFuncAttributeMaxDynamicSharedMemorySize, SMEM_BYTES);

    k_convert<<<768, 256>>>(wqkv, wproj);
    k_stats<<<dim3(64, 8), 256>>>(x);
    k_statfin<<<1, 64>>>();
    k_qkv<<<dim3(128, 8), 512, SMEM_BYTES>>>(x, gam, bet, bqkv);
    k_attn<<<8192, 256>>>();
    k_proj<<<dim3(128, 8), 512, SMEM_BYTES>>>(x, bproj, out);
}

// round 9
// speedup vs baseline: 1.4794x; 1.4496x over previous
#include <cuda_runtime.h>
#include <cuda_bf16.h>
#include <cstdint>

#define HW 16384
#define PITCH 264
#define BS_ELEMS (128*PITCH)
#define GEMM_SMEM ((128*PITCH + 256*PITCH)*2)   // Bs 128 rows + As 256 rows, bf16

// ---------------- scratch (device globals; no allocations allowed) ----------
__device__ __nv_bfloat16 g_qkvT[(size_t)8*HW*768];   // [bv][p][768] bf16
__device__ __nv_bfloat16 g_aoT [(size_t)8*HW*256];   // [bv][p][256] bf16
__device__ __nv_bfloat16 g_wqkv[768*256];
__device__ __nv_bfloat16 g_wproj[256*256];
__device__ float g_part[64][8][2];
__device__ float g_mean[64];
__device__ float g_rstd[64];

// ---------------- helpers ----------------------------------------------------
__device__ __forceinline__ uint32_t s2u(const void* p){
    return (uint32_t)__cvta_generic_to_shared(p);
}
__device__ __forceinline__ void ldsm4(uint32_t r[4], uint32_t addr){
    asm volatile("ldmatrix.sync.aligned.m8n8.x4.shared.b16 {%0,%1,%2,%3}, [%4];"
        : "=r"(r[0]), "=r"(r[1]), "=r"(r[2]), "=r"(r[3]) : "r"(addr));
}
__device__ __forceinline__ void mma_bf16(float c[4], const uint32_t a[4],
                                         uint32_t b0, uint32_t b1){
    asm volatile(
      "mma.sync.aligned.m16n8k16.row.col.f32.bf16.bf16.f32 "
      "{%0,%1,%2,%3},{%4,%5,%6,%7},{%8,%9},{%0,%1,%2,%3};\n"
      : "+f"(c[0]), "+f"(c[1]), "+f"(c[2]), "+f"(c[3])
      : "r"(a[0]), "r"(a[1]), "r"(a[2]), "r"(a[3]), "r"(b0), "r"(b1));
}

// load a [256 m][256 k] bf16 weight tile into smem [256][PITCH], 256 threads
__device__ __forceinline__ void load_wtile(__nv_bfloat16* As,
                                           const __nv_bfloat16* W, int t){
    #pragma unroll
    for (int it = 0; it < 32; ++it){
        const int lin = it*256 + t;
        const int r = lin >> 5, k16 = lin & 31;
        *(uint4*)(As + r*PITCH + k16*8) = *(const uint4*)(W + r*256 + k16*8);
    }
}

// ---------------- weight convert ---------------------------------------------
__global__ void k_convert(const float* __restrict__ wq, const float* __restrict__ wp){
    int i = blockIdx.x*256 + threadIdx.x;
    if (i < 768*256) g_wqkv[i]  = __float2bfloat16(wq[i]);
    if (i < 256*256) g_wproj[i] = __float2bfloat16(wp[i]);
}

// ---------------- GroupNorm statistics ---------------------------------------
__global__ void k_stats(const float* __restrict__ x){
    const int gi = blockIdx.x, ck = blockIdx.y, t = threadIdx.x;
    const float4* p = (const float4*)(x + (size_t)gi*524288 + (size_t)ck*65536);
    float s = 0.f, ss = 0.f;
    #pragma unroll 4
    for (int it = 0; it < 64; ++it){
        float4 v = p[it*256 + t];
        s  += v.x + v.y + v.z + v.w;
        ss += v.x*v.x + v.y*v.y + v.z*v.z + v.w*v.w;
    }
    #pragma unroll
    for (int d = 16; d; d >>= 1){
        s  += __shfl_xor_sync(0xffffffffu, s, d);
        ss += __shfl_xor_sync(0xffffffffu, ss, d);
    }
    __shared__ float sh[16];
    if ((t & 31) == 0){ sh[t>>5] = s; sh[8 + (t>>5)] = ss; }
    __syncthreads();
    if (t == 0){
        float S = 0.f, SS = 0.f;
        for (int i = 0; i < 8; ++i){ S += sh[i]; SS += sh[8+i]; }
        g_part[gi][ck][0] = S; g_part[gi][ck][1] = SS;
    }
}

__global__ void k_statfin(){
    const int t = threadIdx.x;
    float S = 0.f, SS = 0.f;
    for (int i = 0; i < 8; ++i){ S += g_part[t][i][0]; SS += g_part[t][i][1]; }
    const float inv = 1.f/524288.f;
    const float m = S*inv;
    const float v = SS*inv - m*m;
    g_mean[t] = m;
    g_rstd[t] = rsqrtf(v + 1e-5f);
}

// ---------------- fused GroupNorm-apply + QKV GEMM ---------------------------
// 256 threads / 8 warps, warp tile 64 tok x 64 m. CTA tile 128 tok x 256 m,
// 3 M-iterations (768 = 3*256). A-operand = tokens (Bs), B-operand = weights
// (As) so D = [tok][m]: each thread packs bf16x2 along m and stores DIRECTLY
// to the token-major qkv buffer (no smem staging).
__global__ __launch_bounds__(256, 1) void k_qkv(
    const float* __restrict__ x, const float* __restrict__ gamma,
    const float* __restrict__ beta, const float* __restrict__ bqkv)
{
    extern __shared__ __nv_bfloat16 sm[];
    __nv_bfloat16* Bs = sm;             // [128 tok][PITCH]
    __nv_bfloat16* As = sm + BS_ELEMS;  // [256 m][PITCH]
    const int t  = threadIdx.x;
    const int bv = blockIdx.y;
    const int p0 = blockIdx.x * 128;
    const int lane = t & 31, warp = t >> 5;

    // ---- fill Bs: normalize x -> bf16, token-major rows ----
    {
        const int lanep = lane;
        #pragma unroll
        for (int it = 0; it < 16; ++it){
            const int c = (it*8 + warp) * 2;
            const int gidx = bv*8 + (c >> 5);
            const float mu = g_mean[gidx], r = g_rstd[gidx];
            const float sc0 = r*gamma[c],   sh0 = beta[c]   - mu*sc0;
            const float sc1 = r*gamma[c+1], sh1 = beta[c+1] - mu*sc1;
            const float* x0 = x + ((size_t)(bv*256 + c))*HW + p0;
            const float* x1 = x0 + HW;
            #pragma unroll
            for (int i = 0; i < 4; ++i){
                const int j = i*32 + lanep;
                *(__nv_bfloat162*)(Bs + j*PITCH + c) =
                    __floats2bfloat162_rn(x0[j]*sc0 + sh0, x1[j]*sc1 + sh1);
            }
        }
    }
    load_wtile(As, g_wqkv, t);
    __syncthreads();

    const int g = lane >> 2, tq = lane & 3;
    const int lrow  = lane & 15;
    const int khalf = lane >> 4;
    const int twarp = (warp >> 2) * 64;   // token offset (2 groups)
    const int mwarp = (warp & 3) * 64;    // m offset within 256 (4 groups)

    uint32_t aB[4], bB[4];
    #pragma unroll
    for (int i = 0; i < 4; ++i)
        aB[i] = s2u(Bs + (twarp + i*16 + lrow)*PITCH) + khalf*16;
    #pragma unroll
    for (int j = 0; j < 4; ++j)
        bB[j] = s2u(As + (mwarp + j*16 + lrow)*PITCH) + khalf*16;

    for (int mt = 0; mt < 3; ++mt){
        float acc[4][8][4];
        #pragma unroll
        for (int i=0;i<4;i++)
            #pragma unroll
            for (int j=0;j<8;j++)
                #pragma unroll
                for (int r=0;r<4;r++) acc[i][j][r]=0.f;

        #pragma unroll 2
        for (int k0 = 0; k0 < 256; k0 += 16){
            uint32_t ra[4][4], rb[4][4];
            #pragma unroll
            for (int i = 0; i < 4; ++i) ldsm4(ra[i], aB[i] + k0*2);
            #pragma unroll
            for (int j = 0; j < 4; ++j) ldsm4(rb[j], bB[j] + k0*2);
            #pragma unroll
            for (int i = 0; i < 4; ++i)
                #pragma unroll
                for (int j = 0; j < 8; ++j)
                    mma_bf16(acc[i][j], ra[i],
                             rb[j>>1][j&1], rb[j>>1][2 + (j&1)]);
        }
        __syncthreads();

        if (mt < 2) load_wtile(As, g_wqkv + (size_t)(mt + 1)*256*256, t);

        // direct epilogue: bias + bf16x2 pack + token-major global stores
        const float* bb = bqkv + mt*256 + mwarp;
        #pragma unroll
        for (int i = 0; i < 4; ++i){
            const int tokA = p0 + twarp + i*16 + g;
            __nv_bfloat16* d0 = g_qkvT + ((size_t)(bv*HW + tokA))*768 + mt*256 + mwarp;
            __nv_bfloat16* d1 = d0 + (size_t)8*768;
            #pragma unroll
            for (int j = 0; j < 8; ++j){
                const int m0 = j*8 + tq*2;
                *(__nv_bfloat162*)(d0 + m0) =
                    __floats2bfloat162_rn(acc[i][j][0] + bb[m0], acc[i][j][1] + bb[m0+1]);
                *(__nv_bfloat162*)(d1 + m0) =
                    __floats2bfloat162_rn(acc[i][j][2] + bb[m0], acc[i][j][3] + bb[m0+1]);
            }
        }
        __syncthreads();
    }
}

// ---------------- per-pixel 2x2 cross-view attention --------------------------
__device__ __forceinline__ void load8f(float* o, const __nv_bfloat16* p){
    uint4 u = *(const uint4*)p;
    const __nv_bfloat162* h = (const __nv_bfloat162*)&u;
    #pragma unroll
    for (int i = 0; i < 4; ++i){ float2 f = __bfloat1622float2(h[i]); o[2*i] = f.x; o[2*i+1] = f.y; }
}

__global__ __launch_bounds__(256) void k_attn(){
    const int t = threadIdx.x;
    const int gw = blockIdx.x*8 + (t >> 5);
    const int b = gw >> 14, p = gw & 16383;
    const int lane = t & 31;
    const int off = (lane >> 3)*64 + (lane & 7)*8;
    const __nv_bfloat16* r0 = g_qkvT + ((size_t)(b*2*HW + p))*768;
    const __nv_bfloat16* r1 = r0 + (size_t)HW*768;
    float q0[8],q1[8],k0[8],k1[8],v0[8],v1[8];
    load8f(q0, r0 + off);        load8f(q1, r1 + off);
    load8f(k0, r0 + 256 + off);  load8f(k1, r1 + 256 + off);
    load8f(v0, r0 + 512 + off);  load8f(v1, r1 + 512 + off);
    float s00=0.f, s01=0.f, s10=0.f, s11=0.f;
    #pragma unroll
    for (int j = 0; j < 8; ++j){
        s00 += q0[j]*k0[j]; s01 += q0[j]*k1[j];
        s10 += q1[j]*k0[j]; s11 += q1[j]*k1[j];
    }
    #pragma unroll
    for (int d = 1; d < 8; d <<= 1){
        s00 += __shfl_xor_sync(0xffffffffu, s00, d);
        s01 += __shfl_xor_sync(0xffffffffu, s01, d);
        s10 += __shfl_xor_sync(0xffffffffu, s10, d);
        s11 += __shfl_xor_sync(0xffffffffu, s11, d);
    }
    const float sc = 0.125f;
    const float l00=s00*sc, l01=s01*sc, l10=s10*sc, l11=s11*sc;
    const float m0 = fmaxf(l00,l01), m1 = fmaxf(l10,l11);
    const float e00=__expf(l00-m0), e01=__expf(l01-m0);
    const float e10=__expf(l10-m1), e11=__expf(l11-m1);
    const float i0 = 1.f/(e00+e01), i1 = 1.f/(e10+e11);
    const float a00=e00*i0, a01=e01*i0, a10=e10*i1, a11=e11*i1;
    __align__(16) __nv_bfloat16 o0[8], o1[8];
    #pragma unroll
    for (int j = 0; j < 8; ++j){
        o0[j] = __float2bfloat16(a00*v0[j] + a01*v1[j]);
        o1[j] = __float2bfloat16(a10*v0[j] + a11*v1[j]);
    }
    *(uint4*)(g_aoT + ((size_t)(b*2*HW + p))*256 + off)       = *(const uint4*)o0;
    *(uint4*)(g_aoT + ((size_t)((b*2+1)*HW + p))*256 + off)   = *(const uint4*)o1;
}

// ---------------- proj GEMM + bias + residual --------------------------------
// 256 threads / 8 warps, warp tile 64 ch x 64 tok, one pass over all 256 ch.
// A-operand = weights so D = [ch][tok]; fused bias + residual + direct
// float2 NCHW stores (no staging).
__global__ __launch_bounds__(256, 1) void k_proj(
    const float* __restrict__ x, const float* __restrict__ bproj, float* __restrict__ out)
{
    extern __shared__ __nv_bfloat16 sm[];
    __nv_bfloat16* Bs = sm;             // [128 tok][PITCH]
    __nv_bfloat16* As = sm + BS_ELEMS;  // [256 ch][PITCH]
    const int t  = threadIdx.x;
    const int bv = blockIdx.y;
    const int p0 = blockIdx.x * 128;
    const int lane = t & 31, warp = t >> 5;

    {   // B tile: attn-out token-major K-contiguous
        #pragma unroll
        for (int it = 0; it < 16; ++it){
            const int lin = it*256 + t;
            const int r = lin >> 5, k16 = lin & 31;
            *(uint4*)(Bs + r*PITCH + k16*8) =
                *(const uint4*)(g_aoT + ((size_t)(bv*HW + p0 + r))*256 + k16*8);
        }
    }
    load_wtile(As, g_wproj, t);
    __syncthreads();

    const int g = lane >> 2, tq = lane & 3;
    const int lrow  = lane & 15;
    const int khalf = lane >> 4;
    const int mwarp = (warp & 3) * 64;    // channel offset (4 groups)
    const int twarp = (warp >> 2) * 64;   // token offset (2 groups)

    uint32_t aB[4], bB[4];
    #pragma unroll
    for (int i = 0; i < 4; ++i)
        aB[i] = s2u(As + (mwarp + i*16 + lrow)*PITCH) + khalf*16;
    #pragma unroll
    for (int j = 0; j < 4; ++j)
        bB[j] = s2u(Bs + (twarp + j*16 + lrow)*PITCH) + khalf*16;

    float acc[4][8][4];
    #pragma unroll
    for (int i=0;i<4;i++)
        #pragma unroll
        for (int j=0;j<8;j++)
            #pragma unroll
            for (int r=0;r<4;r++) acc[i][j][r]=0.f;

    #pragma unroll 2
    for (int k0 = 0; k0 < 256; k0 += 16){
        uint32_t ra[4][4], rb[4][4];
        #pragma unroll
        for (int i = 0; i < 4; ++i) ldsm4(ra[i], aB[i] + k0*2);
        #pragma unroll
        for (int j = 0; j < 4; ++j) ldsm4(rb[j], bB[j] + k0*2);
        #pragma unroll
        for (int i = 0; i < 4; ++i)
            #pragma unroll
            for (int j = 0; j < 8; ++j)
                mma_bf16(acc[i][j], ra[i],
                         rb[j>>1][j&1], rb[j>>1][2 + (j&1)]);
    }

    // fused epilogue: bias + residual + direct float2 NCHW stores
    #pragma unroll
    for (int i = 0; i < 4; ++i){
        const int ch0 = mwarp + i*16 + g;
        const int ch1 = ch0 + 8;
        const float b0 = bproj[ch0], b1 = bproj[ch1];
        const size_t base0 = ((size_t)(bv*256 + ch0))*HW + p0 + twarp;
        const size_t base1 = ((size_t)(bv*256 + ch1))*HW + p0 + twarp;
        #pragma unroll
        for (int j = 0; j < 8; ++j){
            const int tk = j*8 + tq*2;
            float2 xv0 = *(const float2*)(x + base0 + tk);
            float2 xv1 = *(const float2*)(x + base1 + tk);
            float2 o0 = make_float2(xv0.x + acc[i][j][0] + b0, xv0.y + acc[i][j][1] + b0);
            float2 o1 = make_float2(xv1.x + acc[i][j][2] + b1, xv1.y + acc[i][j][3] + b1);
            *(float2*)(out + base0 + tk) = o0;
            *(float2*)(out + base1 + tk) = o1;
        }
    }
}

// ---------------- launch -------------------------------------------------------
extern "C" void kernel_launch(void* const* d_in, const int* in_sizes, int n_in,
                              void* d_out, int out_size)
{
    const float* x     = (const float*)d_in[0];
    const float* gam   = (const float*)d_in[1];
    const float* bet   = (const float*)d_in[2];
    const float* wqkv  = (const float*)d_in[3];
    const float* bqkv  = (const float*)d_in[4];
    const float* wproj = (const float*)d_in[5];
    const float* bproj = (const float*)d_in[6];
    float* out = (float*)d_out;

    cudaFuncSetAttribute(k_qkv,  cudaFuncAttributeMaxDynamicSharedMemorySize, GEMM_SMEM);
    cudaFuncSetAttribute(k_proj, cudaFuncAttributeMaxDynamicSharedMemorySize, GEMM_SMEM);

    k_convert<<<768, 256>>>(wqkv, wproj);
    k_stats<<<dim3(64, 8), 256>>>(x);
    k_statfin<<<1, 64>>>();
    k_qkv<<<dim3(128, 8), 256, GEMM_SMEM>>>(x, gam, bet, bqkv);
    k_attn<<<8192, 256>>>();
    k_proj<<<dim3(128, 8), 256, GEMM_SMEM>>>(x, bproj, out);
}